// round 8
// baseline (speedup 1.0000x reference)
#include <cuda_runtime.h>

// ----------------------------------------------------------------------------
// Problem constants
// ----------------------------------------------------------------------------
#define N_CHR 50000
#define E_CHR 500000
#define N_SLV 30000
#define E_SLV 300000
#define BATCH 256
#define FEAT  64
#define DIM   128
#define HALF  64
#define ENS   3
#define SLOT  ((long)N_CHR * DIM)   // per-ensemble scratch slot (floats)

// ----------------------------------------------------------------------------
// Device scratch (static globals; no allocation anywhere)
// ----------------------------------------------------------------------------
__device__ float g_ax[N_CHR * FEAT];          // aggregated input features
__device__ float g_bufA[ENS * N_CHR * DIM];   // h0 / g2
__device__ float g_bufB[ENS * N_CHR * DIM];   // g1 / a2
__device__ float g_bufC[ENS * N_CHR * DIM];   // a1
__device__ float g_rep[ENS * BATCH * HALF];   // pooled representation
__device__ float g_hg[BATCH * 2 * ENS * DIM]; // concatenated head outputs [256,768]
__device__ float g_hg2[BATCH * DIM];          // fc1 output
// CSR scratch (sized for the larger graph; reused by slv after chr)
__device__ int g_cnt[N_CHR];                  // per-dst degree
__device__ int g_rowptr[N_CHR + 1];           // CSR row pointers
__device__ int g_pos[N_CHR];                  // atomic cursors for permute
__device__ int g_ssrc[E_CHR];                 // src indices sorted by dst

// ----------------------------------------------------------------------------
// CSR build: histogram -> prefix scan -> permute
// ----------------------------------------------------------------------------
__global__ void hist_kernel(const int* __restrict__ dsti, int* __restrict__ cnt,
                            int E)
{
    int e = blockIdx.x * blockDim.x + threadIdx.x;
    if (e < E) atomicAdd(&cnt[dsti[e]], 1);
}

// Single-block exclusive scan (warp-shuffle based), also fills pos = rowptr.
__global__ void scan_kernel(const int* __restrict__ cnt,
                            int* __restrict__ rowptr,
                            int* __restrict__ pos, int N, int E)
{
    __shared__ int warpTot[32];
    __shared__ int carry;
    int tid = threadIdx.x;
    int lane = tid & 31;
    int wid = tid >> 5;
    if (tid == 0) carry = 0;
    __syncthreads();

    for (int base = 0; base < N; base += 1024) {
        int i = base + tid;
        int v = (i < N) ? cnt[i] : 0;
        int s = v;
#pragma unroll
        for (int off = 1; off < 32; off <<= 1) {
            int t = __shfl_up_sync(0xffffffffu, s, off);
            if (lane >= off) s += t;
        }
        if (lane == 31) warpTot[wid] = s;
        __syncthreads();
        if (wid == 0) {
            int w = warpTot[lane];
#pragma unroll
            for (int off = 1; off < 32; off <<= 1) {
                int t = __shfl_up_sync(0xffffffffu, w, off);
                if (lane >= off) w += t;
            }
            warpTot[lane] = w;
        }
        __syncthreads();
        int warpOff = (wid == 0) ? 0 : warpTot[wid - 1];
        int excl = carry + warpOff + s - v;
        if (i < N) { rowptr[i] = excl; pos[i] = excl; }
        __syncthreads();
        if (tid == 0) carry += warpTot[31];
        __syncthreads();
    }
    if (tid == 0) rowptr[N] = E;
}

__global__ void permute_kernel(const int* __restrict__ srci,
                               const int* __restrict__ dsti,
                               int* __restrict__ pos,
                               int* __restrict__ ssrc, int E)
{
    int e = blockIdx.x * blockDim.x + threadIdx.x;
    if (e < E) {
        int p = atomicAdd(&pos[dsti[e]], 1);
        ssrc[p] = srci[e];
    }
}

// ----------------------------------------------------------------------------
// CSR gather-aggregate: out[z][n][f..f+3] = sum over in-edges of in[z][src][f..f+3]
// ----------------------------------------------------------------------------
template <int LOGTPE, int NZ>
__global__ void gather_csr_kernel(const float* __restrict__ in,
                                  float* __restrict__ out,
                                  const int* __restrict__ rowptr,
                                  const int* __restrict__ ssrc,
                                  int N, long sIn, long sOut)
{
    const int TPE = 1 << LOGTPE;
    const int F = TPE * 4;
    long tid = (long)blockIdx.x * blockDim.x + threadIdx.x;
    int n = (int)(tid >> LOGTPE);
    if (n >= N) return;
    int f = ((int)tid & (TPE - 1)) << 2;
    int beg = rowptr[n];
    int end = rowptr[n + 1];

    float4 acc[NZ];
#pragma unroll
    for (int z = 0; z < NZ; z++) acc[z] = make_float4(0.f, 0.f, 0.f, 0.f);

    for (int i = beg; i < end; i++) {
        long so = (long)ssrc[i] * F + f;
#pragma unroll
        for (int z = 0; z < NZ; z++) {
            float4 v = *(const float4*)(in + z * sIn + so);
            acc[z].x += v.x; acc[z].y += v.y;
            acc[z].z += v.z; acc[z].w += v.w;
        }
    }
    long doff = (long)n * F + f;
#pragma unroll
    for (int z = 0; z < NZ; z++)
        *(float4*)(out + z * sOut + doff) = acc[z];
}

// ----------------------------------------------------------------------------
// Global add pool with fused relu, vectorized + ensemble-fused (NZ=3)
// ----------------------------------------------------------------------------
__global__ void pool_vec_kernel(const float* __restrict__ in,
                                const int* __restrict__ batchids,
                                float* __restrict__ out,
                                int N, long sIn, long sOut)
{
    long tid = (long)blockIdx.x * blockDim.x + threadIdx.x;
    int n = (int)(tid >> 4);
    if (n >= N) return;
    int f = ((int)tid & 15) << 2;
    int b = batchids[n];
    long so = (long)n * HALF + f;
    long doff = (long)b * HALF + f;
#pragma unroll
    for (int z = 0; z < ENS; z++) {
        float4 v = *(const float4*)(in + z * sIn + so);
        v.x = fmaxf(v.x, 0.0f); v.y = fmaxf(v.y, 0.0f);
        v.z = fmaxf(v.z, 0.0f); v.w = fmaxf(v.w, 0.0f);
        float* p = out + z * sOut + doff;
        asm volatile("red.global.add.v4.f32 [%0], {%1,%2,%3,%4};"
                     :: "l"(p), "f"(v.x), "f"(v.y), "f"(v.z), "f"(v.w)
                     : "memory");
    }
}

// ----------------------------------------------------------------------------
// FFMA2 GEMM v2:  C[nrows, BN] = op(A[nrows, K]) @ W[K, BN]
// BM=128, BK=16, 256 threads, 4 row-pairs x TN cols per thread.
// Key upgrades vs v1:
//  - B pre-duplicated into smem as float2(b,b): no per-k mov.b64 duplication.
//  - BK=16: half the __syncthreads per k.
//  - Register prefetch: next tile's global loads issued before compute.
// Inner loop per k: 4 LDS.64 (A) + TN LDS.64 (Bdup) + 4*TN/... FFMA2.
// ----------------------------------------------------------------------------
template <int BN, int RELU_IN, int RELU_OUT>
__global__ __launch_bounds__(256)
void gemm_f2(const float* __restrict__ A, const float* __restrict__ W,
             float* __restrict__ C, int nrows, int K,
             long sA, long sW, long sC)
{
    const int BM = 128, BK = 16, TN = BN / 16;
    const int NWQ = (BN == 128) ? 2 : 1;    // W-loader float4s per thread
    A += blockIdx.z * sA;
    W += blockIdx.z * sW;
    C += blockIdx.z * sC;

    __shared__ __align__(16) float  As[BK][132];
    __shared__ __align__(8)  float2 Ws2[BK][BN];

    int tid = threadIdx.x;
    int tx = tid & 15;
    int ty = tid >> 4;
    int row0 = blockIdx.x * BM;

    // A loader: q in {0,1}; t = tid + q*256; m = t>>2; kq = (t&3)*4
    int am[2], akq[2];
#pragma unroll
    for (int q = 0; q < 2; q++) {
        int t = tid + q * 256;
        am[q] = t >> 2;
        akq[q] = (t & 3) * 4;
    }
    // W loader: q in {0,NWQ}; t = tid + q*256; wk = t>>5 (BN=128) / tid>>4 (BN=64)
    int wk[2], wn4[2];
#pragma unroll
    for (int q = 0; q < NWQ; q++) {
        int t = tid + q * 256;
        if (BN == 128) { wk[q] = t >> 5; wn4[q] = (t & 31) * 4; }
        else           { wk[q] = t >> 4; wn4[q] = (t & 15) * 4; }
    }

    float4 pa[2], pw[2];

    // Prefetch tile 0
#pragma unroll
    for (int q = 0; q < 2; q++) {
        int row = row0 + am[q];
        pa[q] = (row < nrows) ? *(const float4*)(A + (long)row * K + akq[q])
                              : make_float4(0.f, 0.f, 0.f, 0.f);
    }
#pragma unroll
    for (int q = 0; q < NWQ; q++)
        pw[q] = *(const float4*)(W + (long)wk[q] * BN + wn4[q]);

    unsigned long long acc2[4][TN];
#pragma unroll
    for (int i = 0; i < 4; i++)
#pragma unroll
        for (int j = 0; j < TN; j++) acc2[i][j] = 0ull;

    for (int k0 = 0; k0 < K; k0 += BK) {
        __syncthreads();
        // Store prefetched tile to smem
#pragma unroll
        for (int q = 0; q < 2; q++) {
            float4 v = pa[q];
            if (RELU_IN) {
                v.x = fmaxf(v.x, 0.f); v.y = fmaxf(v.y, 0.f);
                v.z = fmaxf(v.z, 0.f); v.w = fmaxf(v.w, 0.f);
            }
            As[akq[q] + 0][am[q]] = v.x;
            As[akq[q] + 1][am[q]] = v.y;
            As[akq[q] + 2][am[q]] = v.z;
            As[akq[q] + 3][am[q]] = v.w;
        }
#pragma unroll
        for (int q = 0; q < NWQ; q++) {
            float4 v = pw[q];
            Ws2[wk[q]][wn4[q] + 0] = make_float2(v.x, v.x);
            Ws2[wk[q]][wn4[q] + 1] = make_float2(v.y, v.y);
            Ws2[wk[q]][wn4[q] + 2] = make_float2(v.z, v.z);
            Ws2[wk[q]][wn4[q] + 3] = make_float2(v.w, v.w);
        }
        __syncthreads();

        // Prefetch next tile (overlaps with compute below)
        int kn = k0 + BK;
        if (kn < K) {
#pragma unroll
            for (int q = 0; q < 2; q++) {
                int row = row0 + am[q];
                pa[q] = (row < nrows)
                    ? *(const float4*)(A + (long)row * K + kn + akq[q])
                    : make_float4(0.f, 0.f, 0.f, 0.f);
            }
#pragma unroll
            for (int q = 0; q < NWQ; q++)
                pw[q] = *(const float4*)(W + (long)(kn + wk[q]) * BN + wn4[q]);
        }

        // Compute BK k-steps: 4 LDS.64 + TN LDS.64 + 4*TN FFMA2 per k
#pragma unroll
        for (int k = 0; k < BK; k++) {
            unsigned long long rav[4], rbv[TN];
#pragma unroll
            for (int i = 0; i < 4; i++)
                rav[i] = *(const unsigned long long*)&As[k][ty * 2 + i * 32];
#pragma unroll
            for (int j = 0; j < TN; j++)
                rbv[j] = *(const unsigned long long*)&Ws2[k][tx + j * 16];
#pragma unroll
            for (int i = 0; i < 4; i++)
#pragma unroll
                for (int j = 0; j < TN; j++)
                    asm("fma.rn.f32x2 %0, %1, %2, %0;"
                        : "+l"(acc2[i][j]) : "l"(rav[i]), "l"(rbv[j]));
        }
    }

    // Epilogue: unpack pairs, optional relu, store
#pragma unroll
    for (int i = 0; i < 4; i++) {
        int r0 = row0 + ty * 2 + i * 32;
#pragma unroll
        for (int j = 0; j < TN; j++) {
            float v0, v1;
            asm("mov.b64 {%0, %1}, %2;" : "=f"(v0), "=f"(v1) : "l"(acc2[i][j]));
            if (RELU_OUT) { v0 = fmaxf(v0, 0.f); v1 = fmaxf(v1, 0.f); }
            int col = tx + j * 16;
            if (r0 < nrows)     C[(long)r0 * BN + col] = v0;
            if (r0 + 1 < nrows) C[(long)(r0 + 1) * BN + col] = v1;
        }
    }
}

// ----------------------------------------------------------------------------
// Small register-tiled GEMM (heads / fc1): C = relu(A @ W + bias), BN=128.
// ----------------------------------------------------------------------------
__global__ void gemm_small(const float* __restrict__ A,
                           const float* __restrict__ W,
                           const float* __restrict__ bias,
                           float* __restrict__ C,
                           int nrows, int K, int ldA, int ldC,
                           long sA, long sW, long sC, long sB)
{
    const int BM = 64, BK = 16, TM = 4, BN = 128, TN = 8;
    A += blockIdx.z * sA;
    W += blockIdx.z * sW;
    C += blockIdx.z * sC;
    if (bias) bias += blockIdx.z * sB;

    __shared__ float As[BK][BM + 1];
    __shared__ float Ws[BK][BN];

    int tid = threadIdx.x;
    int tx = tid & 15;
    int ty = tid >> 4;
    int row0 = blockIdx.x * BM;

    float acc[TM][TN];
#pragma unroll
    for (int i = 0; i < TM; i++)
#pragma unroll
        for (int j = 0; j < TN; j++) acc[i][j] = 0.0f;

    for (int k0 = 0; k0 < K; k0 += BK) {
#pragma unroll
        for (int i = 0; i < (BM * BK) / 256; i++) {
            int t = tid + i * 256;
            int m = t >> 4;
            int k = t & 15;
            int row = row0 + m;
            As[k][m] = (row < nrows) ? A[(long)row * ldA + k0 + k] : 0.0f;
        }
#pragma unroll
        for (int i = 0; i < (BN * BK) / 256; i++) {
            int t = tid + i * 256;
            int n = t & 127;
            int k = t >> 7;
            Ws[k][n] = W[(long)(k0 + k) * BN + n];
        }
        __syncthreads();

#pragma unroll
        for (int k = 0; k < BK; k++) {
            float ra[TM], rb[TN];
#pragma unroll
            for (int i = 0; i < TM; i++) ra[i] = As[k][ty + i * 16];
#pragma unroll
            for (int j = 0; j < TN; j++) rb[j] = Ws[k][tx + j * 16];
#pragma unroll
            for (int i = 0; i < TM; i++)
#pragma unroll
                for (int j = 0; j < TN; j++)
                    acc[i][j] = fmaf(ra[i], rb[j], acc[i][j]);
        }
        __syncthreads();
    }

#pragma unroll
    for (int i = 0; i < TM; i++) {
        int row = row0 + ty + i * 16;
        if (row < nrows) {
#pragma unroll
            for (int j = 0; j < TN; j++) {
                int col = tx + j * 16;
                float v = acc[i][j];
                if (bias) v += bias[col];
                v = fmaxf(v, 0.0f);
                C[(long)row * ldC + col] = v;
            }
        }
    }
}

// ----------------------------------------------------------------------------
// Final fc2: out[row] = dot(hg2[row,:], W[:,0]) + b[0]
// ----------------------------------------------------------------------------
__global__ void fc2_kernel(const float* __restrict__ A,
                           const float* __restrict__ W,
                           const float* __restrict__ b,
                           float* __restrict__ out)
{
    int row = blockIdx.x;
    float v = A[row * DIM + threadIdx.x] * W[threadIdx.x];
#pragma unroll
    for (int o = 16; o > 0; o >>= 1) v += __shfl_down_sync(0xffffffffu, v, o);
    __shared__ float s[4];
    if ((threadIdx.x & 31) == 0) s[threadIdx.x >> 5] = v;
    __syncthreads();
    if (threadIdx.x == 0) out[row] = s[0] + s[1] + s[2] + s[3] + b[0];
}

// ----------------------------------------------------------------------------
// Host-side orchestration
// ----------------------------------------------------------------------------
static void run_branch(const float* x, const int* ei, const int* batchids,
                       const float* W0, const float* W1, const float* W2,
                       const float* fcW, const float* fcb,
                       int N, int E, float* hg_base,
                       float* p_ax, float* p_bufA, float* p_bufB, float* p_bufC,
                       float* p_rep,
                       int* p_cnt, int* p_rowptr, int* p_pos, int* p_ssrc)
{
    const int* src = ei;
    const int* dst = ei + E;
    unsigned gb = (unsigned)((N + 127) / 128);
    unsigned eb = (unsigned)((E + 255) / 256);

    // Build CSR (edges sorted by dst) for gather-side aggregation.
    cudaMemsetAsync(p_cnt, 0, (size_t)N * sizeof(int));
    hist_kernel<<<eb, 256>>>(dst, p_cnt, E);
    scan_kernel<<<1, 1024>>>(p_cnt, p_rowptr, p_pos, N, E);
    permute_kernel<<<eb, 256>>>(src, dst, p_pos, p_ssrc, E);

    // Layer 0 aggregation: ax = agg(x), shared across ensembles (64-wide).
    {
        long total = (long)N * 16;
        gather_csr_kernel<4, 1><<<(unsigned)((total + 255) / 256), 256>>>(
            x, p_ax, p_rowptr, p_ssrc, N, 0, 0);
    }

    // h0[e] = relu(ax @ W0[e])   (z-batched, A shared: sA=0)
    gemm_f2<128, 0, 1><<<dim3(gb, 1, ENS), 256>>>(
        p_ax, W0, p_bufA, N, FEAT, 0, (long)FEAT * DIM, SLOT);

    // g1[e] = h0[e] @ W1[e]
    gemm_f2<128, 0, 0><<<dim3(gb, 1, ENS), 256>>>(
        p_bufA, W1, p_bufB, N, DIM, SLOT, (long)DIM * DIM, SLOT);

    // a1[e] = agg(g1[e])   (128-wide, ensemble-fused gather)
    {
        long total = (long)N * 32;
        gather_csr_kernel<5, ENS><<<(unsigned)((total + 255) / 256), 256>>>(
            p_bufB, p_bufC, p_rowptr, p_ssrc, N, SLOT, SLOT);
    }

    // g2[e] = relu(a1[e]) @ W2[e]   (64-wide output)
    gemm_f2<64, 1, 0><<<dim3(gb, 1, ENS), 256>>>(
        p_bufC, W2, p_bufA, N, DIM, SLOT, (long)DIM * HALF, SLOT);

    // a2[e] = agg(g2[e])   (64-wide, ensemble-fused gather)
    {
        long total = (long)N * 16;
        gather_csr_kernel<4, ENS><<<(unsigned)((total + 255) / 256), 256>>>(
            p_bufA, p_bufB, p_rowptr, p_ssrc, N, SLOT, SLOT);
    }

    // Pool: rep[e] = segment_sum(relu(a2[e]), batchids)
    cudaMemsetAsync(p_rep, 0, (size_t)ENS * BATCH * HALF * sizeof(float));
    {
        long total = (long)N * 16;
        pool_vec_kernel<<<(unsigned)((total + 255) / 256), 256>>>(
            p_bufB, batchids, p_rep, N, SLOT, (long)BATCH * HALF);
    }

    // Heads: hg[:, off + e*128 ...] = relu(rep[e] @ fcW[e] + fcb[e])
    {
        dim3 g((BATCH + 63) / 64, 1, ENS);
        gemm_small<<<g, 256>>>(p_rep, fcW, fcb, hg_base, BATCH, HALF, HALF,
                               2 * ENS * DIM,
                               (long)BATCH * HALF, (long)HALF * DIM, DIM, DIM);
    }
}

extern "C" void kernel_launch(void* const* d_in, const int* in_sizes, int n_in,
                              void* d_out, int out_size)
{
    // Resolve input ordering at runtime (dict order vs signature order).
    int i_chr_x, i_slv_x, i_chr_ei, i_slv_ei, i_chr_b, i_slv_b;
    int i_cW0, i_cW1, i_cW2, i_sW0, i_sW1, i_sW2;
    int i_cfcW, i_cfcB, i_sfcW, i_sfcB, i_fc1W, i_fc1B, i_fc2W, i_fc2B;
    if (in_sizes[2] == 2 * E_CHR) {
        i_chr_x = 0;  i_slv_x = 1;  i_chr_ei = 2; i_slv_ei = 3;
        i_chr_b = 4;  i_slv_b = 5;
        i_cW0 = 6;  i_cW1 = 7;  i_cW2 = 8;
        i_sW0 = 9;  i_sW1 = 10; i_sW2 = 11;
        i_cfcW = 12; i_cfcB = 13; i_sfcW = 14; i_sfcB = 15;
        i_fc1W = 16; i_fc1B = 17; i_fc2W = 18; i_fc2B = 19;
    } else {
        i_chr_x = 0;  i_slv_x = 1;
        i_cW0 = 2;  i_cW1 = 3;  i_cW2 = 4;
        i_sW0 = 5;  i_sW1 = 6;  i_sW2 = 7;
        i_cfcW = 8;  i_cfcB = 9;  i_sfcW = 10; i_sfcB = 11;
        i_fc1W = 12; i_fc1B = 13; i_fc2W = 14; i_fc2B = 15;
        i_chr_ei = 16; i_slv_ei = 17; i_chr_b = 18; i_slv_b = 19;
    }

    const float* chr_x = (const float*)d_in[i_chr_x];
    const float* slv_x = (const float*)d_in[i_slv_x];
    const int* chr_ei = (const int*)d_in[i_chr_ei];
    const int* slv_ei = (const int*)d_in[i_slv_ei];
    const int* chr_bi = (const int*)d_in[i_chr_b];
    const int* slv_bi = (const int*)d_in[i_slv_b];
    const float* cW0 = (const float*)d_in[i_cW0];
    const float* cW1 = (const float*)d_in[i_cW1];
    const float* cW2 = (const float*)d_in[i_cW2];
    const float* sW0 = (const float*)d_in[i_sW0];
    const float* sW1 = (const float*)d_in[i_sW1];
    const float* sW2 = (const float*)d_in[i_sW2];
    const float* cfcW = (const float*)d_in[i_cfcW];
    const float* cfcB = (const float*)d_in[i_cfcB];
    const float* sfcW = (const float*)d_in[i_sfcW];
    const float* sfcB = (const float*)d_in[i_sfcB];
    const float* fc1W = (const float*)d_in[i_fc1W];
    const float* fc1B = (const float*)d_in[i_fc1B];
    const float* fc2W = (const float*)d_in[i_fc2W];
    const float* fc2B = (const float*)d_in[i_fc2B];

    float *p_ax, *p_bufA, *p_bufB, *p_bufC, *p_rep, *p_hg, *p_hg2;
    int *p_cnt, *p_rowptr, *p_pos, *p_ssrc;
    cudaGetSymbolAddress((void**)&p_ax,     g_ax);
    cudaGetSymbolAddress((void**)&p_bufA,   g_bufA);
    cudaGetSymbolAddress((void**)&p_bufB,   g_bufB);
    cudaGetSymbolAddress((void**)&p_bufC,   g_bufC);
    cudaGetSymbolAddress((void**)&p_rep,    g_rep);
    cudaGetSymbolAddress((void**)&p_hg,     g_hg);
    cudaGetSymbolAddress((void**)&p_hg2,    g_hg2);
    cudaGetSymbolAddress((void**)&p_cnt,    g_cnt);
    cudaGetSymbolAddress((void**)&p_rowptr, g_rowptr);
    cudaGetSymbolAddress((void**)&p_pos,    g_pos);
    cudaGetSymbolAddress((void**)&p_ssrc,   g_ssrc);

    // chr branch -> hg columns [0, 384)
    run_branch(chr_x, chr_ei, chr_bi, cW0, cW1, cW2, cfcW, cfcB,
               N_CHR, E_CHR, p_hg, p_ax, p_bufA, p_bufB, p_bufC, p_rep,
               p_cnt, p_rowptr, p_pos, p_ssrc);
    // slv branch -> hg columns [384, 768)  (reuses CSR scratch after chr)
    run_branch(slv_x, slv_ei, slv_bi, sW0, sW1, sW2, sfcW, sfcB,
               N_SLV, E_SLV, p_hg + ENS * DIM, p_ax, p_bufA, p_bufB, p_bufC, p_rep,
               p_cnt, p_rowptr, p_pos, p_ssrc);

    // fc1: hg2 = relu(hg @ fc1W + fc1B)   [256,768]@[768,128]
    {
        dim3 g((BATCH + 63) / 64, 1, 1);
        gemm_small<<<g, 256>>>(p_hg, fc1W, fc1B, p_hg2, BATCH, 2 * ENS * DIM,
                               2 * ENS * DIM, DIM, 0, 0, 0, 0);
    }

    // fc2: out = hg2 @ fc2W + fc2B   [256,128]@[128,1]
    fc2_kernel<<<BATCH, DIM>>>(p_hg2, fc2W, fc2B, (float*)d_out);
}

// round 11
// speedup vs baseline: 1.1871x; 1.1871x over previous
#include <cuda_runtime.h>

// ----------------------------------------------------------------------------
// Problem constants
// ----------------------------------------------------------------------------
#define N_CHR 50000
#define E_CHR 500000
#define N_SLV 30000
#define E_SLV 300000
#define BATCH 256
#define FEAT  64
#define DIM   128
#define HALF  64
#define ENS   3

// ----------------------------------------------------------------------------
// Device scratch (static globals; no allocation anywhere).
// chr and slv branches get DISJOINT scratch so they can run concurrently
// on two streams.
// ----------------------------------------------------------------------------
__device__ float g_ax_c[N_CHR * FEAT];
__device__ float g_bufA_c[ENS * N_CHR * DIM];
__device__ float g_bufB_c[ENS * N_CHR * DIM];
__device__ float g_bufC_c[ENS * N_CHR * DIM];
__device__ float g_rep_c[ENS * BATCH * HALF];
__device__ int   g_cnt_c[N_CHR];
__device__ int   g_rowptr_c[N_CHR + 1];
__device__ int   g_pos_c[N_CHR];
__device__ int   g_ssrc_c[E_CHR];

__device__ float g_ax_s[N_SLV * FEAT];
__device__ float g_bufA_s[ENS * N_SLV * DIM];
__device__ float g_bufB_s[ENS * N_SLV * DIM];
__device__ float g_bufC_s[ENS * N_SLV * DIM];
__device__ float g_rep_s[ENS * BATCH * HALF];
__device__ int   g_cnt_s[N_SLV];
__device__ int   g_rowptr_s[N_SLV + 1];
__device__ int   g_pos_s[N_SLV];
__device__ int   g_ssrc_s[E_SLV];

__device__ float g_hg[BATCH * 2 * ENS * DIM];  // concatenated head outputs
__device__ float g_hg2[BATCH * DIM];           // fc1 output

// ----------------------------------------------------------------------------
// CSR build: histogram -> prefix scan -> permute
// ----------------------------------------------------------------------------
__global__ void hist_kernel(const int* __restrict__ dsti, int* __restrict__ cnt,
                            int E)
{
    int e = blockIdx.x * blockDim.x + threadIdx.x;
    if (e < E) atomicAdd(&cnt[dsti[e]], 1);
}

// Single-block exclusive scan (warp-shuffle based), also fills pos = rowptr.
__global__ void scan_kernel(const int* __restrict__ cnt,
                            int* __restrict__ rowptr,
                            int* __restrict__ pos, int N, int E)
{
    __shared__ int warpTot[32];
    __shared__ int carry;
    int tid = threadIdx.x;
    int lane = tid & 31;
    int wid = tid >> 5;
    if (tid == 0) carry = 0;
    __syncthreads();

    for (int base = 0; base < N; base += 1024) {
        int i = base + tid;
        int v = (i < N) ? cnt[i] : 0;
        int s = v;
#pragma unroll
        for (int off = 1; off < 32; off <<= 1) {
            int t = __shfl_up_sync(0xffffffffu, s, off);
            if (lane >= off) s += t;
        }
        if (lane == 31) warpTot[wid] = s;
        __syncthreads();
        if (wid == 0) {
            int w = warpTot[lane];
#pragma unroll
            for (int off = 1; off < 32; off <<= 1) {
                int t = __shfl_up_sync(0xffffffffu, w, off);
                if (lane >= off) w += t;
            }
            warpTot[lane] = w;
        }
        __syncthreads();
        int warpOff = (wid == 0) ? 0 : warpTot[wid - 1];
        int excl = carry + warpOff + s - v;
        if (i < N) { rowptr[i] = excl; pos[i] = excl; }
        __syncthreads();
        if (tid == 0) carry += warpTot[31];
        __syncthreads();
    }
    if (tid == 0) rowptr[N] = E;
}

__global__ void permute_kernel(const int* __restrict__ srci,
                               const int* __restrict__ dsti,
                               int* __restrict__ pos,
                               int* __restrict__ ssrc, int E)
{
    int e = blockIdx.x * blockDim.x + threadIdx.x;
    if (e < E) {
        int p = atomicAdd(&pos[dsti[e]], 1);
        ssrc[p] = srci[e];
    }
}

// ----------------------------------------------------------------------------
// CSR gather-aggregate: out[z][n][f..f+3] = sum over in-edges of in[z][src][f..f+3]
// ----------------------------------------------------------------------------
template <int LOGTPE, int NZ>
__global__ void gather_csr_kernel(const float* __restrict__ in,
                                  float* __restrict__ out,
                                  const int* __restrict__ rowptr,
                                  const int* __restrict__ ssrc,
                                  int N, long sIn, long sOut)
{
    const int TPE = 1 << LOGTPE;
    const int F = TPE * 4;
    long tid = (long)blockIdx.x * blockDim.x + threadIdx.x;
    int n = (int)(tid >> LOGTPE);
    if (n >= N) return;
    int f = ((int)tid & (TPE - 1)) << 2;
    int beg = rowptr[n];
    int end = rowptr[n + 1];

    float4 acc[NZ];
#pragma unroll
    for (int z = 0; z < NZ; z++) acc[z] = make_float4(0.f, 0.f, 0.f, 0.f);

    for (int i = beg; i < end; i++) {
        long so = (long)ssrc[i] * F + f;
#pragma unroll
        for (int z = 0; z < NZ; z++) {
            float4 v = *(const float4*)(in + z * sIn + so);
            acc[z].x += v.x; acc[z].y += v.y;
            acc[z].z += v.z; acc[z].w += v.w;
        }
    }
    long doff = (long)n * F + f;
#pragma unroll
    for (int z = 0; z < NZ; z++)
        *(float4*)(out + z * sOut + doff) = acc[z];
}

// ----------------------------------------------------------------------------
// Global add pool with fused relu, vectorized + ensemble-fused (NZ=3)
// ----------------------------------------------------------------------------
__global__ void pool_vec_kernel(const float* __restrict__ in,
                                const int* __restrict__ batchids,
                                float* __restrict__ out,
                                int N, long sIn, long sOut)
{
    long tid = (long)blockIdx.x * blockDim.x + threadIdx.x;
    int n = (int)(tid >> 4);
    if (n >= N) return;
    int f = ((int)tid & 15) << 2;
    int b = batchids[n];
    long so = (long)n * HALF + f;
    long doff = (long)b * HALF + f;
#pragma unroll
    for (int z = 0; z < ENS; z++) {
        float4 v = *(const float4*)(in + z * sIn + so);
        v.x = fmaxf(v.x, 0.0f); v.y = fmaxf(v.y, 0.0f);
        v.z = fmaxf(v.z, 0.0f); v.w = fmaxf(v.w, 0.0f);
        float* p = out + z * sOut + doff;
        asm volatile("red.global.add.v4.f32 [%0], {%1,%2,%3,%4};"
                     :: "l"(p), "f"(v.x), "f"(v.y), "f"(v.z), "f"(v.w)
                     : "memory");
    }
}

// ----------------------------------------------------------------------------
// FFMA2 (packed f32x2) GEMM (round-6 proven):
// C[nrows, BN] = op(A[nrows, K]) @ W[K, BN]
// BM=128, BK=8, 256 threads, 4 row-pairs x TN cols per thread (fma.rn.f32x2).
// ----------------------------------------------------------------------------
template <int BN, int RELU_IN, int RELU_OUT>
__global__ __launch_bounds__(256)
void gemm_f2(const float* __restrict__ A, const float* __restrict__ W,
             float* __restrict__ C, int nrows, int K,
             long sA, long sW, long sC)
{
    const int BM = 128, BK = 8, TN = BN / 16;
    A += blockIdx.z * sA;
    W += blockIdx.z * sW;
    C += blockIdx.z * sC;

    __shared__ __align__(16) float As[BK][132];
    __shared__ __align__(16) float Ws[BK][BN];

    int tid = threadIdx.x;
    int tx = tid & 15;
    int ty = tid >> 4;
    int row0 = blockIdx.x * BM;

    int arow = tid >> 1;
    int akq = (tid & 1) * 4;
    int wk, wn4;
    if (BN == 128) { wk = tid >> 5; wn4 = (tid & 31) * 4; }
    else           { wk = tid >> 4; wn4 = (tid & 15) * 4; }

    unsigned long long acc2[4][TN];
#pragma unroll
    for (int i = 0; i < 4; i++)
#pragma unroll
        for (int j = 0; j < TN; j++) acc2[i][j] = 0ull;

    for (int k0 = 0; k0 < K; k0 += BK) {
        {
            int row = row0 + arow;
            float4 v = make_float4(0.f, 0.f, 0.f, 0.f);
            if (row < nrows)
                v = *(const float4*)(A + (long)row * K + k0 + akq);
            if (RELU_IN) {
                v.x = fmaxf(v.x, 0.f); v.y = fmaxf(v.y, 0.f);
                v.z = fmaxf(v.z, 0.f); v.w = fmaxf(v.w, 0.f);
            }
            As[akq + 0][arow] = v.x;
            As[akq + 1][arow] = v.y;
            As[akq + 2][arow] = v.z;
            As[akq + 3][arow] = v.w;
        }
        if (BN == 128 || tid < 128) {
            float4 v = *(const float4*)(W + (long)(k0 + wk) * BN + wn4);
            *(float4*)&Ws[wk][wn4] = v;
        }
        __syncthreads();

#pragma unroll
        for (int k = 0; k < BK; k++) {
            unsigned long long rav[4], rbv[TN];
#pragma unroll
            for (int i = 0; i < 4; i++) {
                float2 t = *(const float2*)&As[k][ty * 2 + i * 32];
                asm("mov.b64 %0, {%1, %2};" : "=l"(rav[i]) : "f"(t.x), "f"(t.y));
            }
#pragma unroll
            for (int j = 0; j < TN; j++) {
                float b = Ws[k][tx + j * 16];
                asm("mov.b64 %0, {%1, %1};" : "=l"(rbv[j]) : "f"(b));
            }
#pragma unroll
            for (int i = 0; i < 4; i++)
#pragma unroll
                for (int j = 0; j < TN; j++)
                    asm("fma.rn.f32x2 %0, %1, %2, %0;"
                        : "+l"(acc2[i][j]) : "l"(rav[i]), "l"(rbv[j]));
        }
        __syncthreads();
    }

#pragma unroll
    for (int i = 0; i < 4; i++) {
        int r0 = row0 + ty * 2 + i * 32;
#pragma unroll
        for (int j = 0; j < TN; j++) {
            float v0, v1;
            asm("mov.b64 {%0, %1}, %2;" : "=f"(v0), "=f"(v1) : "l"(acc2[i][j]));
            if (RELU_OUT) { v0 = fmaxf(v0, 0.f); v1 = fmaxf(v1, 0.f); }
            int col = tx + j * 16;
            if (r0 < nrows)     C[(long)r0 * BN + col] = v0;
            if (r0 + 1 < nrows) C[(long)(r0 + 1) * BN + col] = v1;
        }
    }
}

// ----------------------------------------------------------------------------
// Small register-tiled GEMM (heads / fc1): C = relu(A @ W + bias), BN=128.
// ----------------------------------------------------------------------------
__global__ void gemm_small(const float* __restrict__ A,
                           const float* __restrict__ W,
                           const float* __restrict__ bias,
                           float* __restrict__ C,
                           int nrows, int K, int ldA, int ldC,
                           long sA, long sW, long sC, long sB)
{
    const int BM = 64, BK = 16, TM = 4, BN = 128, TN = 8;
    A += blockIdx.z * sA;
    W += blockIdx.z * sW;
    C += blockIdx.z * sC;
    if (bias) bias += blockIdx.z * sB;

    __shared__ float As[BK][BM + 1];
    __shared__ float Ws[BK][BN];

    int tid = threadIdx.x;
    int tx = tid & 15;
    int ty = tid >> 4;
    int row0 = blockIdx.x * BM;

    float acc[TM][TN];
#pragma unroll
    for (int i = 0; i < TM; i++)
#pragma unroll
        for (int j = 0; j < TN; j++) acc[i][j] = 0.0f;

    for (int k0 = 0; k0 < K; k0 += BK) {
#pragma unroll
        for (int i = 0; i < (BM * BK) / 256; i++) {
            int t = tid + i * 256;
            int m = t >> 4;
            int k = t & 15;
            int row = row0 + m;
            As[k][m] = (row < nrows) ? A[(long)row * ldA + k0 + k] : 0.0f;
        }
#pragma unroll
        for (int i = 0; i < (BN * BK) / 256; i++) {
            int t = tid + i * 256;
            int n = t & 127;
            int k = t >> 7;
            Ws[k][n] = W[(long)(k0 + k) * BN + n];
        }
        __syncthreads();

#pragma unroll
        for (int k = 0; k < BK; k++) {
            float ra[TM], rb[TN];
#pragma unroll
            for (int i = 0; i < TM; i++) ra[i] = As[k][ty + i * 16];
#pragma unroll
            for (int j = 0; j < TN; j++) rb[j] = Ws[k][tx + j * 16];
#pragma unroll
            for (int i = 0; i < TM; i++)
#pragma unroll
                for (int j = 0; j < TN; j++)
                    acc[i][j] = fmaf(ra[i], rb[j], acc[i][j]);
        }
        __syncthreads();
    }

#pragma unroll
    for (int i = 0; i < TM; i++) {
        int row = row0 + ty + i * 16;
        if (row < nrows) {
#pragma unroll
            for (int j = 0; j < TN; j++) {
                int col = tx + j * 16;
                float v = acc[i][j];
                if (bias) v += bias[col];
                v = fmaxf(v, 0.0f);
                C[(long)row * ldC + col] = v;
            }
        }
    }
}

// ----------------------------------------------------------------------------
// Final fc2: out[row] = dot(hg2[row,:], W[:,0]) + b[0]
// ----------------------------------------------------------------------------
__global__ void fc2_kernel(const float* __restrict__ A,
                           const float* __restrict__ W,
                           const float* __restrict__ b,
                           float* __restrict__ out)
{
    int row = blockIdx.x;
    float v = A[row * DIM + threadIdx.x] * W[threadIdx.x];
#pragma unroll
    for (int o = 16; o > 0; o >>= 1) v += __shfl_down_sync(0xffffffffu, v, o);
    __shared__ float s[4];
    if ((threadIdx.x & 31) == 0) s[threadIdx.x >> 5] = v;
    __syncthreads();
    if (threadIdx.x == 0) out[row] = s[0] + s[1] + s[2] + s[3] + b[0];
}

// ----------------------------------------------------------------------------
// Host-side orchestration (stream-parameterized; chr and slv run concurrently)
// ----------------------------------------------------------------------------
static void run_branch(const float* x, const int* ei, const int* batchids,
                       const float* W0, const float* W1, const float* W2,
                       const float* fcW, const float* fcb,
                       int N, int E, float* hg_base,
                       float* p_ax, float* p_bufA, float* p_bufB, float* p_bufC,
                       float* p_rep,
                       int* p_cnt, int* p_rowptr, int* p_pos, int* p_ssrc,
                       cudaStream_t st)
{
    const int* src = ei;
    const int* dst = ei + E;
    const long slot = (long)N * DIM;
    unsigned gb = (unsigned)((N + 127) / 128);
    unsigned eb = (unsigned)((E + 255) / 256);

    // Build CSR (edges sorted by dst) for gather-side aggregation.
    cudaMemsetAsync(p_cnt, 0, (size_t)N * sizeof(int), st);
    hist_kernel<<<eb, 256, 0, st>>>(dst, p_cnt, E);
    scan_kernel<<<1, 1024, 0, st>>>(p_cnt, p_rowptr, p_pos, N, E);
    permute_kernel<<<eb, 256, 0, st>>>(src, dst, p_pos, p_ssrc, E);

    // Layer 0 aggregation: ax = agg(x), shared across ensembles (64-wide).
    {
        long total = (long)N * 16;
        gather_csr_kernel<4, 1><<<(unsigned)((total + 255) / 256), 256, 0, st>>>(
            x, p_ax, p_rowptr, p_ssrc, N, 0, 0);
    }

    // h0[e] = relu(ax @ W0[e])   (z-batched, A shared: sA=0)
    gemm_f2<128, 0, 1><<<dim3(gb, 1, ENS), 256, 0, st>>>(
        p_ax, W0, p_bufA, N, FEAT, 0, (long)FEAT * DIM, slot);

    // g1[e] = h0[e] @ W1[e]
    gemm_f2<128, 0, 0><<<dim3(gb, 1, ENS), 256, 0, st>>>(
        p_bufA, W1, p_bufB, N, DIM, slot, (long)DIM * DIM, slot);

    // a1[e] = agg(g1[e])   (128-wide, ensemble-fused gather)
    {
        long total = (long)N * 32;
        gather_csr_kernel<5, ENS><<<(unsigned)((total + 255) / 256), 256, 0, st>>>(
            p_bufB, p_bufC, p_rowptr, p_ssrc, N, slot, slot);
    }

    // g2[e] = relu(a1[e]) @ W2[e]   (64-wide output)
    gemm_f2<64, 1, 0><<<dim3(gb, 1, ENS), 256, 0, st>>>(
        p_bufC, W2, p_bufA, N, DIM, slot, (long)DIM * HALF, slot);

    // a2[e] = agg(g2[e])   (64-wide, ensemble-fused gather)
    {
        long total = (long)N * 16;
        gather_csr_kernel<4, ENS><<<(unsigned)((total + 255) / 256), 256, 0, st>>>(
            p_bufA, p_bufB, p_rowptr, p_ssrc, N, slot, slot);
    }

    // Pool: rep[e] = segment_sum(relu(a2[e]), batchids)
    cudaMemsetAsync(p_rep, 0, (size_t)ENS * BATCH * HALF * sizeof(float), st);
    {
        long total = (long)N * 16;
        pool_vec_kernel<<<(unsigned)((total + 255) / 256), 256, 0, st>>>(
            p_bufB, batchids, p_rep, N, slot, (long)BATCH * HALF);
    }

    // Heads: hg[:, off + e*128 ...] = relu(rep[e] @ fcW[e] + fcb[e])
    {
        dim3 g((BATCH + 63) / 64, 1, ENS);
        gemm_small<<<g, 256, 0, st>>>(p_rep, fcW, fcb, hg_base, BATCH, HALF, HALF,
                                      2 * ENS * DIM,
                                      (long)BATCH * HALF, (long)HALF * DIM, DIM, DIM);
    }
}

extern "C" void kernel_launch(void* const* d_in, const int* in_sizes, int n_in,
                              void* d_out, int out_size)
{
    // Lazily create the second stream + fork/join events ONCE (first call runs
    // outside graph capture; later captured calls reuse them — same work every
    // call, no device memory involved).
    static cudaStream_t s2 = nullptr;
    static cudaEvent_t evFork = nullptr, evJoin = nullptr;
    if (!s2) {
        cudaStreamCreateWithFlags(&s2, cudaStreamNonBlocking);
        cudaEventCreateWithFlags(&evFork, cudaEventDisableTiming);
        cudaEventCreateWithFlags(&evJoin, cudaEventDisableTiming);
    }

    // Resolve input ordering at runtime (dict order vs signature order).
    int i_chr_x, i_slv_x, i_chr_ei, i_slv_ei, i_chr_b, i_slv_b;
    int i_cW0, i_cW1, i_cW2, i_sW0, i_sW1, i_sW2;
    int i_cfcW, i_cfcB, i_sfcW, i_sfcB, i_fc1W, i_fc1B, i_fc2W, i_fc2B;
    if (in_sizes[2] == 2 * E_CHR) {
        i_chr_x = 0;  i_slv_x = 1;  i_chr_ei = 2; i_slv_ei = 3;
        i_chr_b = 4;  i_slv_b = 5;
        i_cW0 = 6;  i_cW1 = 7;  i_cW2 = 8;
        i_sW0 = 9;  i_sW1 = 10; i_sW2 = 11;
        i_cfcW = 12; i_cfcB = 13; i_sfcW = 14; i_sfcB = 15;
        i_fc1W = 16; i_fc1B = 17; i_fc2W = 18; i_fc2B = 19;
    } else {
        i_chr_x = 0;  i_slv_x = 1;
        i_cW0 = 2;  i_cW1 = 3;  i_cW2 = 4;
        i_sW0 = 5;  i_sW1 = 6;  i_sW2 = 7;
        i_cfcW = 8;  i_cfcB = 9;  i_sfcW = 10; i_sfcB = 11;
        i_fc1W = 12; i_fc1B = 13; i_fc2W = 14; i_fc2B = 15;
        i_chr_ei = 16; i_slv_ei = 17; i_chr_b = 18; i_slv_b = 19;
    }

    const float* chr_x = (const float*)d_in[i_chr_x];
    const float* slv_x = (const float*)d_in[i_slv_x];
    const int* chr_ei = (const int*)d_in[i_chr_ei];
    const int* slv_ei = (const int*)d_in[i_slv_ei];
    const int* chr_bi = (const int*)d_in[i_chr_b];
    const int* slv_bi = (const int*)d_in[i_slv_b];
    const float* cW0 = (const float*)d_in[i_cW0];
    const float* cW1 = (const float*)d_in[i_cW1];
    const float* cW2 = (const float*)d_in[i_cW2];
    const float* sW0 = (const float*)d_in[i_sW0];
    const float* sW1 = (const float*)d_in[i_sW1];
    const float* sW2 = (const float*)d_in[i_sW2];
    const float* cfcW = (const float*)d_in[i_cfcW];
    const float* cfcB = (const float*)d_in[i_cfcB];
    const float* sfcW = (const float*)d_in[i_sfcW];
    const float* sfcB = (const float*)d_in[i_sfcB];
    const float* fc1W = (const float*)d_in[i_fc1W];
    const float* fc1B = (const float*)d_in[i_fc1B];
    const float* fc2W = (const float*)d_in[i_fc2W];
    const float* fc2B = (const float*)d_in[i_fc2B];

    float *pc_ax, *pc_A, *pc_B, *pc_C, *pc_rep;
    int *pc_cnt, *pc_rp, *pc_pos, *pc_ss;
    float *ps_ax, *ps_A, *ps_B, *ps_C, *ps_rep;
    int *ps_cnt, *ps_rp, *ps_pos, *ps_ss;
    float *p_hg, *p_hg2;
    cudaGetSymbolAddress((void**)&pc_ax,  g_ax_c);
    cudaGetSymbolAddress((void**)&pc_A,   g_bufA_c);
    cudaGetSymbolAddress((void**)&pc_B,   g_bufB_c);
    cudaGetSymbolAddress((void**)&pc_C,   g_bufC_c);
    cudaGetSymbolAddress((void**)&pc_rep, g_rep_c);
    cudaGetSymbolAddress((void**)&pc_cnt, g_cnt_c);
    cudaGetSymbolAddress((void**)&pc_rp,  g_rowptr_c);
    cudaGetSymbolAddress((void**)&pc_pos, g_pos_c);
    cudaGetSymbolAddress((void**)&pc_ss,  g_ssrc_c);
    cudaGetSymbolAddress((void**)&ps_ax,  g_ax_s);
    cudaGetSymbolAddress((void**)&ps_A,   g_bufA_s);
    cudaGetSymbolAddress((void**)&ps_B,   g_bufB_s);
    cudaGetSymbolAddress((void**)&ps_C,   g_bufC_s);
    cudaGetSymbolAddress((void**)&ps_rep, g_rep_s);
    cudaGetSymbolAddress((void**)&ps_cnt, g_cnt_s);
    cudaGetSymbolAddress((void**)&ps_rp,  g_rowptr_s);
    cudaGetSymbolAddress((void**)&ps_pos, g_pos_s);
    cudaGetSymbolAddress((void**)&ps_ss,  g_ssrc_s);
    cudaGetSymbolAddress((void**)&p_hg,   g_hg);
    cudaGetSymbolAddress((void**)&p_hg2,  g_hg2);

    // Fork: slv branch runs on s2 concurrently with chr on the main stream.
    cudaEventRecord(evFork, 0);
    cudaStreamWaitEvent(s2, evFork, 0);

    // chr branch -> hg columns [0, 384)   (main stream)
    run_branch(chr_x, chr_ei, chr_bi, cW0, cW1, cW2, cfcW, cfcB,
               N_CHR, E_CHR, p_hg, pc_ax, pc_A, pc_B, pc_C, pc_rep,
               pc_cnt, pc_rp, pc_pos, pc_ss, (cudaStream_t)0);
    // slv branch -> hg columns [384, 768)  (stream s2, disjoint scratch)
    run_branch(slv_x, slv_ei, slv_bi, sW0, sW1, sW2, sfcW, sfcB,
               N_SLV, E_SLV, p_hg + ENS * DIM, ps_ax, ps_A, ps_B, ps_C, ps_rep,
               ps_cnt, ps_rp, ps_pos, ps_ss, s2);

    // Join: main stream waits for slv before fc1.
    cudaEventRecord(evJoin, s2);
    cudaStreamWaitEvent((cudaStream_t)0, evJoin, 0);

    // fc1: hg2 = relu(hg @ fc1W + fc1B)   [256,768]@[768,128]
    {
        dim3 g((BATCH + 63) / 64, 1, 1);
        gemm_small<<<g, 256>>>(p_hg, fc1W, fc1B, p_hg2, BATCH, 2 * ENS * DIM,
                               2 * ENS * DIM, DIM, 0, 0, 0, 0);
    }

    // fc2: out = hg2 @ fc2W + fc2B   [256,128]@[128,1]
    fc2_kernel<<<BATCH, DIM>>>(p_hg2, fc2W, fc2B, (float*)d_out);
}